// round 1
// baseline (speedup 1.0000x reference)
#include <cuda_runtime.h>
#include <math.h>
#include <stdint.h>

// ---------------------------------------------------------------------------
// GSDecoder: 8-layer windowed transformer, N=4096 tokens, C=512, H=8, DH=64,
// windows of 512 tokens (token order is already window-blocked), MLP=2048,
// out head 56 cols, gaussian-splat postprocess. Full fp32 round-0 baseline.
// ---------------------------------------------------------------------------

#define NTOK   4096
#define CDIM   512
#define HEADS  8
#define DHEAD  64
#define LAYERS 8
#define MLPDIM 2048
#define OUTC   56
#define NGAUSS 4

// ------------------------- scratch (device globals) ------------------------
__device__ float g_h   [NTOK * CDIM];    // residual stream
__device__ float g_a   [NTOK * CDIM];    // LN output
__device__ float g_qkv [NTOK * 3 * CDIM];
__device__ float g_attn[NTOK * CDIM];
__device__ float g_mlp [NTOK * MLPDIM];
__device__ float g_out [NTOK * OUTC];

// ------------------------------ helpers ------------------------------------
__device__ __forceinline__ float gelu_f(float x) {
    float x3 = x * x * x;
    return 0.5f * x * (1.0f + tanhf(0.7978845608028654f * (x + 0.044715f * x3)));
}

// ------------------------------ embed + PE ---------------------------------
__global__ void embed_kernel(const float* __restrict__ feats,
                             const int*   __restrict__ coords,
                             const float* __restrict__ ex,
                             const float* __restrict__ ey,
                             const float* __restrict__ ez,
                             const float* __restrict__ w_in,
                             const float* __restrict__ b_in)
{
    int n = blockIdx.x;
    int c = threadIdx.x;           // 512 threads
    const float* f = feats + (size_t)n * 8;
    float acc = b_in[c];
#pragma unroll
    for (int l = 0; l < 8; l++) acc += f[l] * w_in[l * CDIM + c];

    int cx = coords[n * 4 + 1];
    int cy = coords[n * 4 + 2];
    int cz = coords[n * 4 + 3];
    float pe;
    if (c < 170)      pe = ex[cx * 170 + c];
    else if (c < 340) pe = ey[cy * 170 + (c - 170)];
    else              pe = ez[cz * 172 + (c - 340)];
    g_h[(size_t)n * CDIM + c] = acc + pe;
}

// ------------------------------ layernorm ----------------------------------
__global__ void __launch_bounds__(256)
ln_kernel(const float* __restrict__ x,
          const float* __restrict__ g,
          const float* __restrict__ b,
          float* __restrict__ out,
          float eps, int has_gb)
{
    int n   = blockIdx.x;
    int tid = threadIdx.x;         // 256 threads, 2 elems each
    const float* xr = x + (size_t)n * CDIM;
    float v0 = xr[tid], v1 = xr[tid + 256];
    float s  = v0 + v1;
    float s2 = v0 * v0 + v1 * v1;
#pragma unroll
    for (int off = 16; off; off >>= 1) {
        s  += __shfl_xor_sync(0xffffffffu, s,  off);
        s2 += __shfl_xor_sync(0xffffffffu, s2, off);
    }
    __shared__ float sh[16];
    __shared__ float stats[2];
    int wid = tid >> 5, lane = tid & 31;
    if (lane == 0) { sh[wid] = s; sh[wid + 8] = s2; }
    __syncthreads();
    if (tid == 0) {
        float ts = 0.f, ts2 = 0.f;
#pragma unroll
        for (int i = 0; i < 8; i++) { ts += sh[i]; ts2 += sh[i + 8]; }
        float mean = ts * (1.0f / 512.0f);
        float var  = ts2 * (1.0f / 512.0f) - mean * mean;
        if (var < 0.f) var = 0.f;
        stats[0] = mean;
        stats[1] = rsqrtf(var + eps);
    }
    __syncthreads();
    float mean = stats[0], r = stats[1];
    float o0 = (v0 - mean) * r;
    float o1 = (v1 - mean) * r;
    if (has_gb) {
        o0 = o0 * g[tid]       + b[tid];
        o1 = o1 * g[tid + 256] + b[tid + 256];
    }
    float* orow = out + (size_t)n * CDIM;
    orow[tid] = o0; orow[tid + 256] = o1;
}

// ------------------------------- SGEMM -------------------------------------
// C[M,N] = epi( A[M,K] @ B[K,N] + bias[N] ), epi: 0=bias, 1=+=residual(C), 2=gelu
#define BM 128
#define BN 128
#define BKK 16
#define TM 8
#define TN 8

__global__ void __launch_bounds__(256)
sgemm_kernel(const float* __restrict__ A, const float* __restrict__ B,
             const float* __restrict__ bias, float* __restrict__ C,
             int M, int N, int K, int epi)
{
    __shared__ float As[BKK][BM + 4];   // transposed: As[k][m]
    __shared__ float Bs[BKK][BN + 4];

    int tid = threadIdx.x;
    int n0 = blockIdx.x * BN;
    int m0 = blockIdx.y * BM;
    int tx = tid & 15, ty = tid >> 4;

    float acc[TM][TN];
#pragma unroll
    for (int i = 0; i < TM; i++)
#pragma unroll
        for (int j = 0; j < TN; j++) acc[i][j] = 0.f;

    int arow = tid >> 2;            // 0..63
    int acol = (tid & 3) << 2;      // 0,4,8,12
    int brow = tid >> 4;            // 0..15
    int bcol = (tid & 15) << 2;     // 0..60

    for (int k0 = 0; k0 < K; k0 += BKK) {
#pragma unroll
        for (int r = 0; r < 2; r++) {
            int row = arow + r * 64;
            float4 v = *(const float4*)(A + (size_t)(m0 + row) * K + k0 + acol);
            As[acol + 0][row] = v.x;
            As[acol + 1][row] = v.y;
            As[acol + 2][row] = v.z;
            As[acol + 3][row] = v.w;
        }
#pragma unroll
        for (int r = 0; r < 2; r++) {
            int col = bcol + r * 64;
            float4 v = *(const float4*)(B + (size_t)(k0 + brow) * N + n0 + col);
            *(float4*)&Bs[brow][col] = v;
        }
        __syncthreads();
#pragma unroll
        for (int kk = 0; kk < BKK; kk++) {
            float ar[TM], br[TN];
            *(float4*)&ar[0] = *(const float4*)&As[kk][ty * TM];
            *(float4*)&ar[4] = *(const float4*)&As[kk][ty * TM + 4];
            *(float4*)&br[0] = *(const float4*)&Bs[kk][tx * TN];
            *(float4*)&br[4] = *(const float4*)&Bs[kk][tx * TN + 4];
#pragma unroll
            for (int i = 0; i < TM; i++)
#pragma unroll
                for (int j = 0; j < TN; j++)
                    acc[i][j] += ar[i] * br[j];
        }
        __syncthreads();
    }

#pragma unroll
    for (int i = 0; i < TM; i++) {
        int m = m0 + ty * TM + i;
#pragma unroll
        for (int j = 0; j < TN; j++) {
            int n = n0 + tx * TN + j;
            float c = acc[i][j] + bias[n];
            if (epi == 1) c += C[(size_t)m * N + n];
            else if (epi == 2) c = gelu_f(c);
            C[(size_t)m * N + n] = c;
        }
    }
}

// ----------------------------- attention -----------------------------------
// grid: (qchunk=8, head=8, window=8), 256 threads. Flash-style, fp32,
// K/V streamed in 32-row tiles, static smem < 48KB.
__global__ void __launch_bounds__(256)
attn_kernel(const float* __restrict__ qkv, float* __restrict__ o)
{
    __shared__ float Qs[64][65];
    __shared__ float Ks[32][65];
    __shared__ float Vs[32][65];
    __shared__ float Ps[64][33];

    int qc = blockIdx.x, h = blockIdx.y, w = blockIdx.z;
    int tid = threadIdx.x;
    int tx = tid & 15, ty = tid >> 4;
    int tok0  = w * 512;
    int qbase = qc * 64;
    int qoff = h * DHEAD;
    int koff = CDIM + h * DHEAD;
    int voff = 2 * CDIM + h * DHEAD;

    // load Q (64 x 64)
    for (int idx = tid; idx < 64 * 16; idx += 256) {
        int r  = idx >> 4;
        int c4 = (idx & 15) << 2;
        float4 v = *(const float4*)(qkv + (size_t)(tok0 + qbase + r) * (3 * CDIM) + qoff + c4);
        Qs[r][c4] = v.x; Qs[r][c4 + 1] = v.y; Qs[r][c4 + 2] = v.z; Qs[r][c4 + 3] = v.w;
    }

    float m_run[4], l_run[4], accO[4][4];
#pragma unroll
    for (int i = 0; i < 4; i++) {
        m_run[i] = -1e30f; l_run[i] = 0.f;
#pragma unroll
        for (int j = 0; j < 4; j++) accO[i][j] = 0.f;
    }

    for (int kt = 0; kt < 16; kt++) {
        __syncthreads();   // prev PV done (and Q visible on first iter)
        for (int idx = tid; idx < 32 * 16; idx += 256) {
            int r  = idx >> 4;
            int c4 = (idx & 15) << 2;
            size_t rowb = (size_t)(tok0 + kt * 32 + r) * (3 * CDIM);
            float4 vk = *(const float4*)(qkv + rowb + koff + c4);
            Ks[r][c4] = vk.x; Ks[r][c4 + 1] = vk.y; Ks[r][c4 + 2] = vk.z; Ks[r][c4 + 3] = vk.w;
            float4 vv = *(const float4*)(qkv + rowb + voff + c4);
            Vs[r][c4] = vv.x; Vs[r][c4 + 1] = vv.y; Vs[r][c4 + 2] = vv.z; Vs[r][c4 + 3] = vv.w;
        }
        __syncthreads();

        float s[4][2];
#pragma unroll
        for (int i = 0; i < 4; i++) { s[i][0] = 0.f; s[i][1] = 0.f; }
#pragma unroll
        for (int d = 0; d < 64; d++) {
            float qv0 = Qs[ty * 4 + 0][d];
            float qv1 = Qs[ty * 4 + 1][d];
            float qv2 = Qs[ty * 4 + 2][d];
            float qv3 = Qs[ty * 4 + 3][d];
            float kv0 = Ks[tx * 2 + 0][d];
            float kv1 = Ks[tx * 2 + 1][d];
            s[0][0] += qv0 * kv0; s[0][1] += qv0 * kv1;
            s[1][0] += qv1 * kv0; s[1][1] += qv1 * kv1;
            s[2][0] += qv2 * kv0; s[2][1] += qv2 * kv1;
            s[3][0] += qv3 * kv0; s[3][1] += qv3 * kv1;
        }

#pragma unroll
        for (int i = 0; i < 4; i++) {
            s[i][0] *= 0.125f; s[i][1] *= 0.125f;
            float rm = fmaxf(s[i][0], s[i][1]);
#pragma unroll
            for (int off = 8; off; off >>= 1)
                rm = fmaxf(rm, __shfl_xor_sync(0xffffffffu, rm, off));
            float nm = fmaxf(m_run[i], rm);
            float alpha = expf(m_run[i] - nm);
            float p0 = expf(s[i][0] - nm);
            float p1 = expf(s[i][1] - nm);
            Ps[ty * 4 + i][tx * 2 + 0] = p0;
            Ps[ty * 4 + i][tx * 2 + 1] = p1;
            float rs = p0 + p1;
#pragma unroll
            for (int off = 8; off; off >>= 1)
                rs += __shfl_xor_sync(0xffffffffu, rs, off);
            m_run[i] = nm;
            l_run[i] = l_run[i] * alpha + rs;
#pragma unroll
            for (int j = 0; j < 4; j++) accO[i][j] *= alpha;
        }
        __syncthreads();

#pragma unroll
        for (int k = 0; k < 32; k++) {
            float pv0 = Ps[ty * 4 + 0][k];
            float pv1 = Ps[ty * 4 + 1][k];
            float pv2 = Ps[ty * 4 + 2][k];
            float pv3 = Ps[ty * 4 + 3][k];
            float vv0 = Vs[k][tx * 4 + 0];
            float vv1 = Vs[k][tx * 4 + 1];
            float vv2 = Vs[k][tx * 4 + 2];
            float vv3 = Vs[k][tx * 4 + 3];
            accO[0][0] += pv0 * vv0; accO[0][1] += pv0 * vv1; accO[0][2] += pv0 * vv2; accO[0][3] += pv0 * vv3;
            accO[1][0] += pv1 * vv0; accO[1][1] += pv1 * vv1; accO[1][2] += pv1 * vv2; accO[1][3] += pv1 * vv3;
            accO[2][0] += pv2 * vv0; accO[2][1] += pv2 * vv1; accO[2][2] += pv2 * vv2; accO[2][3] += pv2 * vv3;
            accO[3][0] += pv3 * vv0; accO[3][1] += pv3 * vv1; accO[3][2] += pv3 * vv2; accO[3][3] += pv3 * vv3;
        }
    }

#pragma unroll
    for (int i = 0; i < 4; i++) {
        float inv = 1.0f / l_run[i];
        size_t row = (size_t)(tok0 + qbase + ty * 4 + i) * CDIM + h * DHEAD;
#pragma unroll
        for (int j = 0; j < 4; j++)
            o[row + tx * 4 + j] = accO[i][j] * inv;
    }
}

// ----------------------------- out head ------------------------------------
__global__ void outhead_kernel(const float* __restrict__ a,
                               const float* __restrict__ w,
                               const float* __restrict__ b)
{
    __shared__ float row[CDIM];
    int n = blockIdx.x;
    for (int i = threadIdx.x; i < CDIM; i += 64)
        row[i] = a[(size_t)n * CDIM + i];
    __syncthreads();
    int oc = threadIdx.x;
    if (oc < OUTC) {
        float acc = b[oc];
#pragma unroll 8
        for (int k = 0; k < CDIM; k++)
            acc += row[k] * w[k * OUTC + oc];
        g_out[n * OUTC + oc] = acc;
    }
}

// ---------------------------- postprocess ----------------------------------
// output packing (float32): xyz[16384*3] | fdc[16384*3] | scal[16384*3] |
// rot[16384*4] | opa[16384]
__global__ void post_kernel(const int* __restrict__ coords,
                            const float* __restrict__ perturb,
                            float* __restrict__ out)
{
    int idx = blockIdx.x * 256 + threadIdx.x;
    if (idx >= NTOK * NGAUSS) return;
    int n = idx >> 2, g = idx & 3;
    const float* r = g_out + n * OUTC;
#pragma unroll
    for (int j = 0; j < 3; j++) {
        float off = tanhf(r[g * 3 + j] + perturb[g * 3 + j]) * 4.8828125e-4f;
        float xb  = ((float)coords[n * 4 + 1 + j] + 0.5f) * 0.0625f;
        out[idx * 3 + j]          = xb + off;
        out[49152 + idx * 3 + j]  = r[12 + g * 3 + j];
        out[98304 + idx * 3 + j]  = r[24 + g * 3 + j];
    }
#pragma unroll
    for (int j = 0; j < 4; j++)
        out[147456 + idx * 4 + j] = r[36 + g * 4 + j];
    out[212992 + idx] = r[52 + g];
}

// ------------------------------- launch ------------------------------------
extern "C" void kernel_launch(void* const* d_in, const int* in_sizes, int n_in,
                              void* d_out, int out_size)
{
    const float* feats   = (const float*)d_in[0];
    const int*   coords  = (const int*)  d_in[1];
    const float* emb_x   = (const float*)d_in[2];
    const float* emb_y   = (const float*)d_in[3];
    const float* emb_z   = (const float*)d_in[4];
    const float* w_in    = (const float*)d_in[5];
    const float* b_in    = (const float*)d_in[6];
    const float* ln1_g   = (const float*)d_in[7];
    const float* ln1_b   = (const float*)d_in[8];
    const float* w_qkv   = (const float*)d_in[9];
    const float* b_qkv   = (const float*)d_in[10];
    const float* w_o     = (const float*)d_in[11];
    const float* b_o     = (const float*)d_in[12];
    const float* ln2_g   = (const float*)d_in[13];
    const float* ln2_b   = (const float*)d_in[14];
    const float* w_m1    = (const float*)d_in[15];
    const float* b_m1    = (const float*)d_in[16];
    const float* w_m2    = (const float*)d_in[17];
    const float* b_m2    = (const float*)d_in[18];
    const float* w_out   = (const float*)d_in[19];
    const float* b_out   = (const float*)d_in[20];
    const float* perturb = (const float*)d_in[21];
    float* out = (float*)d_out;

    float *ph, *pa, *pqkv, *pattn, *pmlp;
    cudaGetSymbolAddress((void**)&ph,    g_h);
    cudaGetSymbolAddress((void**)&pa,    g_a);
    cudaGetSymbolAddress((void**)&pqkv,  g_qkv);
    cudaGetSymbolAddress((void**)&pattn, g_attn);
    cudaGetSymbolAddress((void**)&pmlp,  g_mlp);

    embed_kernel<<<NTOK, CDIM>>>(feats, coords, emb_x, emb_y, emb_z, w_in, b_in);

    for (int l = 0; l < LAYERS; l++) {
        ln_kernel<<<NTOK, 256>>>(ph, ln1_g + l * CDIM, ln1_b + l * CDIM,
                                 pa, 1e-6f, 1);
        sgemm_kernel<<<dim3(3 * CDIM / BN, NTOK / BM), 256>>>(
            pa, w_qkv + (size_t)l * CDIM * 3 * CDIM, b_qkv + l * 3 * CDIM,
            pqkv, NTOK, 3 * CDIM, CDIM, 0);
        attn_kernel<<<dim3(8, HEADS, 8), 256>>>(pqkv, pattn);
        sgemm_kernel<<<dim3(CDIM / BN, NTOK / BM), 256>>>(
            pattn, w_o + (size_t)l * CDIM * CDIM, b_o + l * CDIM,
            ph, NTOK, CDIM, CDIM, 1);
        ln_kernel<<<NTOK, 256>>>(ph, ln2_g + l * CDIM, ln2_b + l * CDIM,
                                 pa, 1e-6f, 1);
        sgemm_kernel<<<dim3(MLPDIM / BN, NTOK / BM), 256>>>(
            pa, w_m1 + (size_t)l * CDIM * MLPDIM, b_m1 + l * MLPDIM,
            pmlp, NTOK, MLPDIM, CDIM, 2);
        sgemm_kernel<<<dim3(CDIM / BN, NTOK / BM), 256>>>(
            pmlp, w_m2 + (size_t)l * MLPDIM * CDIM, b_m2 + l * CDIM,
            ph, NTOK, CDIM, MLPDIM, 1);
    }

    ln_kernel<<<NTOK, 256>>>(ph, nullptr, nullptr, pa, 1e-5f, 0);
    outhead_kernel<<<NTOK, 64>>>(pa, w_out, b_out);
    post_kernel<<<(NTOK * NGAUSS + 255) / 256, 256>>>(coords, perturb, out);
}

// round 2
// speedup vs baseline: 1.9049x; 1.9049x over previous
#include <cuda_runtime.h>
#include <cuda_bf16.h>
#include <math.h>
#include <stdint.h>

// ---------------------------------------------------------------------------
// GSDecoder: 8-layer windowed transformer, N=4096 tokens, C=512, H=8, DH=64,
// windows of 512 tokens, MLP=2048, out head 56 cols, splat postprocess.
// Round 2: all big GEMMs on tensor cores via bf16x3 split (fp32 accuracy).
// ---------------------------------------------------------------------------

#define NTOK   4096
#define CDIM   512
#define HEADS  8
#define DHEAD  64
#define LAYERS 8
#define MLPDIM 2048
#define OUTC   56
#define NGAUSS 4

// ------------------------- scratch (device globals) ------------------------
__device__ float g_h   [NTOK * CDIM];
__device__ float g_a   [NTOK * CDIM];
__device__ float g_qkv [NTOK * 3 * CDIM];
__device__ float g_attn[NTOK * CDIM];
__device__ float g_mlp [NTOK * MLPDIM];
__device__ float g_out [NTOK * OUTC];

// ------------------------------ helpers ------------------------------------
__device__ __forceinline__ float gelu_f(float x) {
    float x3 = x * x * x;
    return 0.5f * x * (1.0f + tanhf(0.7978845608028654f * (x + 0.044715f * x3)));
}

__device__ __forceinline__ void ldsm_x4(unsigned* r, unsigned addr) {
    asm volatile("ldmatrix.sync.aligned.m8n8.x4.shared.b16 {%0,%1,%2,%3}, [%4];"
                 : "=r"(r[0]), "=r"(r[1]), "=r"(r[2]), "=r"(r[3]) : "r"(addr));
}
__device__ __forceinline__ void ldsm_x2t(unsigned* r, unsigned addr) {
    asm volatile("ldmatrix.sync.aligned.m8n8.x2.trans.shared.b16 {%0,%1}, [%2];"
                 : "=r"(r[0]), "=r"(r[1]) : "r"(addr));
}
__device__ __forceinline__ void mma16816(float* c, const unsigned* a, const unsigned* b) {
    asm volatile("mma.sync.aligned.m16n8k16.row.col.f32.bf16.bf16.f32 "
                 "{%0,%1,%2,%3}, {%4,%5,%6,%7}, {%8,%9}, {%0,%1,%2,%3};"
                 : "+f"(c[0]), "+f"(c[1]), "+f"(c[2]), "+f"(c[3])
                 : "r"(a[0]), "r"(a[1]), "r"(a[2]), "r"(a[3]),
                   "r"(b[0]), "r"(b[1]));
}

// split a float4 into hi/lo bf16 quads stored to smem (8B-aligned dests)
__device__ __forceinline__ void split4(float4 v, __nv_bfloat16* h, __nv_bfloat16* l) {
    float x0 = v.x, x1 = v.y, x2 = v.z, x3 = v.w;
    __nv_bfloat16 h0 = __float2bfloat16_rn(x0);
    __nv_bfloat16 h1 = __float2bfloat16_rn(x1);
    __nv_bfloat16 h2 = __float2bfloat16_rn(x2);
    __nv_bfloat16 h3 = __float2bfloat16_rn(x3);
    __nv_bfloat16 l0 = __float2bfloat16_rn(x0 - __bfloat162float(h0));
    __nv_bfloat16 l1 = __float2bfloat16_rn(x1 - __bfloat162float(h1));
    __nv_bfloat16 l2 = __float2bfloat16_rn(x2 - __bfloat162float(h2));
    __nv_bfloat16 l3 = __float2bfloat16_rn(x3 - __bfloat162float(h3));
    ((__nv_bfloat162*)h)[0] = __halves2bfloat162(h0, h1);
    ((__nv_bfloat162*)h)[1] = __halves2bfloat162(h2, h3);
    ((__nv_bfloat162*)l)[0] = __halves2bfloat162(l0, l1);
    ((__nv_bfloat162*)l)[1] = __halves2bfloat162(l2, l3);
}

// ------------------------------ embed + PE ---------------------------------
__global__ void embed_kernel(const float* __restrict__ feats,
                             const int*   __restrict__ coords,
                             const float* __restrict__ ex,
                             const float* __restrict__ ey,
                             const float* __restrict__ ez,
                             const float* __restrict__ w_in,
                             const float* __restrict__ b_in)
{
    int n = blockIdx.x;
    int c = threadIdx.x;
    const float* f = feats + (size_t)n * 8;
    float acc = b_in[c];
#pragma unroll
    for (int l = 0; l < 8; l++) acc += f[l] * w_in[l * CDIM + c];

    int cx = coords[n * 4 + 1];
    int cy = coords[n * 4 + 2];
    int cz = coords[n * 4 + 3];
    float pe;
    if (c < 170)      pe = ex[cx * 170 + c];
    else if (c < 340) pe = ey[cy * 170 + (c - 170)];
    else              pe = ez[cz * 172 + (c - 340)];
    g_h[(size_t)n * CDIM + c] = acc + pe;
}

// ------------------------------ layernorm ----------------------------------
__global__ void __launch_bounds__(256)
ln_kernel(const float* __restrict__ x,
          const float* __restrict__ g,
          const float* __restrict__ b,
          float* __restrict__ out,
          float eps, int has_gb)
{
    int n   = blockIdx.x;
    int tid = threadIdx.x;
    const float* xr = x + (size_t)n * CDIM;
    float v0 = xr[tid], v1 = xr[tid + 256];
    float s  = v0 + v1;
    float s2 = v0 * v0 + v1 * v1;
#pragma unroll
    for (int off = 16; off; off >>= 1) {
        s  += __shfl_xor_sync(0xffffffffu, s,  off);
        s2 += __shfl_xor_sync(0xffffffffu, s2, off);
    }
    __shared__ float sh[16];
    __shared__ float stats[2];
    int wid = tid >> 5, lane = tid & 31;
    if (lane == 0) { sh[wid] = s; sh[wid + 8] = s2; }
    __syncthreads();
    if (tid == 0) {
        float ts = 0.f, ts2 = 0.f;
#pragma unroll
        for (int i = 0; i < 8; i++) { ts += sh[i]; ts2 += sh[i + 8]; }
        float mean = ts * (1.0f / 512.0f);
        float var  = ts2 * (1.0f / 512.0f) - mean * mean;
        if (var < 0.f) var = 0.f;
        stats[0] = mean;
        stats[1] = rsqrtf(var + eps);
    }
    __syncthreads();
    float mean = stats[0], r = stats[1];
    float o0 = (v0 - mean) * r;
    float o1 = (v1 - mean) * r;
    if (has_gb) {
        o0 = o0 * g[tid]       + b[tid];
        o1 = o1 * g[tid + 256] + b[tid + 256];
    }
    float* orow = out + (size_t)n * CDIM;
    orow[tid] = o0; orow[tid + 256] = o1;
}

// -------------------- tensor-core GEMM (bf16x3 split) ----------------------
// C[M,N] = epi( A[M,K] @ B[K,N] + bias[N] );  epi: 0=bias, 1=+residual, 2=gelu
#define BM 128
#define BN 128
#define BK 16
#define APAD 24     // bf16 elements per A row in smem (16 + 8 pad)
#define BPAD 136    // bf16 elements per B row in smem (128 + 8 pad)

__global__ void __launch_bounds__(256)
gemm_tc_kernel(const float* __restrict__ A, const float* __restrict__ B,
               const float* __restrict__ bias, float* __restrict__ C,
               int M, int N, int K, int epi)
{
    __shared__ __align__(16) __nv_bfloat16 sA[2][2][BM * APAD]; // [buf][hi/lo]
    __shared__ __align__(16) __nv_bfloat16 sB[2][2][BK * BPAD];

    const int tid  = threadIdx.x;
    const int wid  = tid >> 5;
    const int lane = tid & 31;
    const int n0 = blockIdx.x * BN;
    const int m0 = blockIdx.y * BM;
    const int wm = (wid >> 2) * 64;   // 2 warp rows of 64
    const int wn = (wid & 3) * 32;    // 4 warp cols of 32

    float acc[4][4][4];
#pragma unroll
    for (int i = 0; i < 4; i++)
#pragma unroll
        for (int j = 0; j < 4; j++)
#pragma unroll
            for (int k = 0; k < 4; k++) acc[i][j][k] = 0.f;

    // staging index precompute
    const int a_row0 = tid >> 2;           // + 64*i
    const int a_kc   = (tid & 3) << 2;
    const int b_kr0  = tid >> 5;           // + 8*i
    const int b_nc   = (lane) << 2;        // (tid&31)*4

    float4 ra[2], rb[2];

    // prologue: load tile 0
#pragma unroll
    for (int i = 0; i < 2; i++) {
        ra[i] = *(const float4*)(A + (size_t)(m0 + a_row0 + 64 * i) * K + a_kc);
        rb[i] = *(const float4*)(B + (size_t)(b_kr0 + 8 * i) * N + n0 + b_nc);
    }
#pragma unroll
    for (int i = 0; i < 2; i++) {
        int offA = (a_row0 + 64 * i) * APAD + a_kc;
        split4(ra[i], &sA[0][0][offA], &sA[0][1][offA]);
        int offB = (b_kr0 + 8 * i) * BPAD + b_nc;
        split4(rb[i], &sB[0][0][offB], &sB[0][1][offB]);
    }
    __syncthreads();

    const int KT = K / BK;
    for (int kt = 0; kt < KT; kt++) {
        int buf = kt & 1;
        if (kt + 1 < KT) {
            int k0 = (kt + 1) * BK;
#pragma unroll
            for (int i = 0; i < 2; i++) {
                ra[i] = *(const float4*)(A + (size_t)(m0 + a_row0 + 64 * i) * K + k0 + a_kc);
                rb[i] = *(const float4*)(B + (size_t)(k0 + b_kr0 + 8 * i) * N + n0 + b_nc);
            }
        }

        // ---- compute on buf ----
        unsigned ah[4][4], al[4][4], bh[4][2], bl[4][2];
        {
            unsigned aAddrH = (unsigned)__cvta_generic_to_shared(
                &sA[buf][0][(wm + (lane & 15)) * APAD + ((lane >> 4) << 3)]);
            unsigned aAddrL = (unsigned)__cvta_generic_to_shared(
                &sA[buf][1][(wm + (lane & 15)) * APAD + ((lane >> 4) << 3)]);
#pragma unroll
            for (int mb = 0; mb < 4; mb++) {
                ldsm_x4(ah[mb], aAddrH + mb * (16 * APAD * 2));
                ldsm_x4(al[mb], aAddrL + mb * (16 * APAD * 2));
            }
            unsigned bAddrH = (unsigned)__cvta_generic_to_shared(
                &sB[buf][0][(lane & 15) * BPAD + wn]);
            unsigned bAddrL = (unsigned)__cvta_generic_to_shared(
                &sB[buf][1][(lane & 15) * BPAD + wn]);
#pragma unroll
            for (int nb = 0; nb < 4; nb++) {
                ldsm_x2t(bh[nb], bAddrH + nb * 16);
                ldsm_x2t(bl[nb], bAddrL + nb * 16);
            }
        }
#pragma unroll
        for (int mb = 0; mb < 4; mb++)
#pragma unroll
            for (int nb = 0; nb < 4; nb++)
                mma16816(acc[mb][nb], ah[mb], bh[nb]);
#pragma unroll
        for (int mb = 0; mb < 4; mb++)
#pragma unroll
            for (int nb = 0; nb < 4; nb++)
                mma16816(acc[mb][nb], al[mb], bh[nb]);
#pragma unroll
        for (int mb = 0; mb < 4; mb++)
#pragma unroll
            for (int nb = 0; nb < 4; nb++)
                mma16816(acc[mb][nb], ah[mb], bl[nb]);

        // ---- stage next tile ----
        if (kt + 1 < KT) {
            int nbuf = buf ^ 1;
#pragma unroll
            for (int i = 0; i < 2; i++) {
                int offA = (a_row0 + 64 * i) * APAD + a_kc;
                split4(ra[i], &sA[nbuf][0][offA], &sA[nbuf][1][offA]);
                int offB = (b_kr0 + 8 * i) * BPAD + b_nc;
                split4(rb[i], &sB[nbuf][0][offB], &sB[nbuf][1][offB]);
            }
        }
        __syncthreads();
    }

    // ---- epilogue ----
#pragma unroll
    for (int mb = 0; mb < 4; mb++) {
        int m = m0 + wm + mb * 16 + (lane >> 2);
#pragma unroll
        for (int nb = 0; nb < 4; nb++) {
            int n = n0 + wn + nb * 8 + (lane & 3) * 2;
            float2 bv = *(const float2*)(bias + n);
            float c0 = acc[mb][nb][0] + bv.x;
            float c1 = acc[mb][nb][1] + bv.y;
            float c2 = acc[mb][nb][2] + bv.x;
            float c3 = acc[mb][nb][3] + bv.y;
            float* p0 = C + (size_t)m * N + n;
            float* p1 = C + (size_t)(m + 8) * N + n;
            if (epi == 1) {
                float2 r0 = *(float2*)p0;
                float2 r1 = *(float2*)p1;
                c0 += r0.x; c1 += r0.y; c2 += r1.x; c3 += r1.y;
            } else if (epi == 2) {
                c0 = gelu_f(c0); c1 = gelu_f(c1);
                c2 = gelu_f(c2); c3 = gelu_f(c3);
            }
            *(float2*)p0 = make_float2(c0, c1);
            *(float2*)p1 = make_float2(c2, c3);
        }
    }
}

// ----------------------------- attention -----------------------------------
__global__ void __launch_bounds__(256)
attn_kernel(const float* __restrict__ qkv, float* __restrict__ o)
{
    __shared__ float Qs[64][65];
    __shared__ float Ks[32][65];
    __shared__ float Vs[32][65];
    __shared__ float Ps[64][33];

    int qc = blockIdx.x, h = blockIdx.y, w = blockIdx.z;
    int tid = threadIdx.x;
    int tx = tid & 15, ty = tid >> 4;
    int tok0  = w * 512;
    int qbase = qc * 64;
    int qoff = h * DHEAD;
    int koff = CDIM + h * DHEAD;
    int voff = 2 * CDIM + h * DHEAD;

    for (int idx = tid; idx < 64 * 16; idx += 256) {
        int r  = idx >> 4;
        int c4 = (idx & 15) << 2;
        float4 v = *(const float4*)(qkv + (size_t)(tok0 + qbase + r) * (3 * CDIM) + qoff + c4);
        Qs[r][c4] = v.x; Qs[r][c4 + 1] = v.y; Qs[r][c4 + 2] = v.z; Qs[r][c4 + 3] = v.w;
    }

    float m_run[4], l_run[4], accO[4][4];
#pragma unroll
    for (int i = 0; i < 4; i++) {
        m_run[i] = -1e30f; l_run[i] = 0.f;
#pragma unroll
        for (int j = 0; j < 4; j++) accO[i][j] = 0.f;
    }

    for (int kt = 0; kt < 16; kt++) {
        __syncthreads();
        for (int idx = tid; idx < 32 * 16; idx += 256) {
            int r  = idx >> 4;
            int c4 = (idx & 15) << 2;
            size_t rowb = (size_t)(tok0 + kt * 32 + r) * (3 * CDIM);
            float4 vk = *(const float4*)(qkv + rowb + koff + c4);
            Ks[r][c4] = vk.x; Ks[r][c4 + 1] = vk.y; Ks[r][c4 + 2] = vk.z; Ks[r][c4 + 3] = vk.w;
            float4 vv = *(const float4*)(qkv + rowb + voff + c4);
            Vs[r][c4] = vv.x; Vs[r][c4 + 1] = vv.y; Vs[r][c4 + 2] = vv.z; Vs[r][c4 + 3] = vv.w;
        }
        __syncthreads();

        float s[4][2];
#pragma unroll
        for (int i = 0; i < 4; i++) { s[i][0] = 0.f; s[i][1] = 0.f; }
#pragma unroll
        for (int d = 0; d < 64; d++) {
            float qv0 = Qs[ty * 4 + 0][d];
            float qv1 = Qs[ty * 4 + 1][d];
            float qv2 = Qs[ty * 4 + 2][d];
            float qv3 = Qs[ty * 4 + 3][d];
            float kv0 = Ks[tx * 2 + 0][d];
            float kv1 = Ks[tx * 2 + 1][d];
            s[0][0] += qv0 * kv0; s[0][1] += qv0 * kv1;
            s[1][0] += qv1 * kv0; s[1][1] += qv1 * kv1;
            s[2][0] += qv2 * kv0; s[2][1] += qv2 * kv1;
            s[3][0] += qv3 * kv0; s[3][1] += qv3 * kv1;
        }

#pragma unroll
        for (int i = 0; i < 4; i++) {
            s[i][0] *= 0.125f; s[i][1] *= 0.125f;
            float rm = fmaxf(s[i][0], s[i][1]);
#pragma unroll
            for (int off = 8; off; off >>= 1)
                rm = fmaxf(rm, __shfl_xor_sync(0xffffffffu, rm, off));
            float nm = fmaxf(m_run[i], rm);
            float alpha = expf(m_run[i] - nm);
            float p0 = expf(s[i][0] - nm);
            float p1 = expf(s[i][1] - nm);
            Ps[ty * 4 + i][tx * 2 + 0] = p0;
            Ps[ty * 4 + i][tx * 2 + 1] = p1;
            float rs = p0 + p1;
#pragma unroll
            for (int off = 8; off; off >>= 1)
                rs += __shfl_xor_sync(0xffffffffu, rs, off);
            m_run[i] = nm;
            l_run[i] = l_run[i] * alpha + rs;
#pragma unroll
            for (int j = 0; j < 4; j++) accO[i][j] *= alpha;
        }
        __syncthreads();

#pragma unroll
        for (int k = 0; k < 32; k++) {
            float pv0 = Ps[ty * 4 + 0][k];
            float pv1 = Ps[ty * 4 + 1][k];
            float pv2 = Ps[ty * 4 + 2][k];
            float pv3 = Ps[ty * 4 + 3][k];
            float vv0 = Vs[k][tx * 4 + 0];
            float vv1 = Vs[k][tx * 4 + 1];
            float vv2 = Vs[k][tx * 4 + 2];
            float vv3 = Vs[k][tx * 4 + 3];
            accO[0][0] += pv0 * vv0; accO[0][1] += pv0 * vv1; accO[0][2] += pv0 * vv2; accO[0][3] += pv0 * vv3;
            accO[1][0] += pv1 * vv0; accO[1][1] += pv1 * vv1; accO[1][2] += pv1 * vv2; accO[1][3] += pv1 * vv3;
            accO[2][0] += pv2 * vv0; accO[2][1] += pv2 * vv1; accO[2][2] += pv2 * vv2; accO[2][3] += pv2 * vv3;
            accO[3][0] += pv3 * vv0; accO[3][1] += pv3 * vv1; accO[3][2] += pv3 * vv2; accO[3][3] += pv3 * vv3;
        }
    }

#pragma unroll
    for (int i = 0; i < 4; i++) {
        float inv = 1.0f / l_run[i];
        size_t row = (size_t)(tok0 + qbase + ty * 4 + i) * CDIM + h * DHEAD;
#pragma unroll
        for (int j = 0; j < 4; j++)
            o[row + tx * 4 + j] = accO[i][j] * inv;
    }
}

// ----------------------------- out head ------------------------------------
__global__ void outhead_kernel(const float* __restrict__ a,
                               const float* __restrict__ w,
                               const float* __restrict__ b)
{
    __shared__ float row[CDIM];
    int n = blockIdx.x;
    for (int i = threadIdx.x; i < CDIM; i += 64)
        row[i] = a[(size_t)n * CDIM + i];
    __syncthreads();
    int oc = threadIdx.x;
    if (oc < OUTC) {
        float acc = b[oc];
#pragma unroll 8
        for (int k = 0; k < CDIM; k++)
            acc += row[k] * w[k * OUTC + oc];
        g_out[n * OUTC + oc] = acc;
    }
}

// ---------------------------- postprocess ----------------------------------
__global__ void post_kernel(const int* __restrict__ coords,
                            const float* __restrict__ perturb,
                            float* __restrict__ out)
{
    int idx = blockIdx.x * 256 + threadIdx.x;
    if (idx >= NTOK * NGAUSS) return;
    int n = idx >> 2, g = idx & 3;
    const float* r = g_out + n * OUTC;
#pragma unroll
    for (int j = 0; j < 3; j++) {
        float off = tanhf(r[g * 3 + j] + perturb[g * 3 + j]) * 4.8828125e-4f;
        float xb  = ((float)coords[n * 4 + 1 + j] + 0.5f) * 0.0625f;
        out[idx * 3 + j]          = xb + off;
        out[49152 + idx * 3 + j]  = r[12 + g * 3 + j];
        out[98304 + idx * 3 + j]  = r[24 + g * 3 + j];
    }
#pragma unroll
    for (int j = 0; j < 4; j++)
        out[147456 + idx * 4 + j] = r[36 + g * 4 + j];
    out[212992 + idx] = r[52 + g];
}

// ------------------------------- launch ------------------------------------
extern "C" void kernel_launch(void* const* d_in, const int* in_sizes, int n_in,
                              void* d_out, int out_size)
{
    const float* feats   = (const float*)d_in[0];
    const int*   coords  = (const int*)  d_in[1];
    const float* emb_x   = (const float*)d_in[2];
    const float* emb_y   = (const float*)d_in[3];
    const float* emb_z   = (const float*)d_in[4];
    const float* w_in    = (const float*)d_in[5];
    const float* b_in    = (const float*)d_in[6];
    const float* ln1_g   = (const float*)d_in[7];
    const float* ln1_b   = (const float*)d_in[8];
    const float* w_qkv   = (const float*)d_in[9];
    const float* b_qkv   = (const float*)d_in[10];
    const float* w_o     = (const float*)d_in[11];
    const float* b_o     = (const float*)d_in[12];
    const float* ln2_g   = (const float*)d_in[13];
    const float* ln2_b   = (const float*)d_in[14];
    const float* w_m1    = (const float*)d_in[15];
    const float* b_m1    = (const float*)d_in[16];
    const float* w_m2    = (const float*)d_in[17];
    const float* b_m2    = (const float*)d_in[18];
    const float* w_out   = (const float*)d_in[19];
    const float* b_out   = (const float*)d_in[20];
    const float* perturb = (const float*)d_in[21];
    float* out = (float*)d_out;

    float *ph, *pa, *pqkv, *pattn, *pmlp;
    cudaGetSymbolAddress((void**)&ph,    g_h);
    cudaGetSymbolAddress((void**)&pa,    g_a);
    cudaGetSymbolAddress((void**)&pqkv,  g_qkv);
    cudaGetSymbolAddress((void**)&pattn, g_attn);
    cudaGetSymbolAddress((void**)&pmlp,  g_mlp);

    embed_kernel<<<NTOK, CDIM>>>(feats, coords, emb_x, emb_y, emb_z, w_in, b_in);

    for (int l = 0; l < LAYERS; l++) {
        ln_kernel<<<NTOK, 256>>>(ph, ln1_g + l * CDIM, ln1_b + l * CDIM,
                                 pa, 1e-6f, 1);
        gemm_tc_kernel<<<dim3(3 * CDIM / BN, NTOK / BM), 256>>>(
            pa, w_qkv + (size_t)l * CDIM * 3 * CDIM, b_qkv + l * 3 * CDIM,
            pqkv, NTOK, 3 * CDIM, CDIM, 0);
        attn_kernel<<<dim3(8, HEADS, 8), 256>>>(pqkv, pattn);
        gemm_tc_kernel<<<dim3(CDIM / BN, NTOK / BM), 256>>>(
            pattn, w_o + (size_t)l * CDIM * CDIM, b_o + l * CDIM,
            ph, NTOK, CDIM, CDIM, 1);
        ln_kernel<<<NTOK, 256>>>(ph, ln2_g + l * CDIM, ln2_b + l * CDIM,
                                 pa, 1e-6f, 1);
        gemm_tc_kernel<<<dim3(MLPDIM / BN, NTOK / BM), 256>>>(
            pa, w_m1 + (size_t)l * CDIM * MLPDIM, b_m1 + l * MLPDIM,
            pmlp, NTOK, MLPDIM, CDIM, 2);
        gemm_tc_kernel<<<dim3(CDIM / BN, NTOK / BM), 256>>>(
            pmlp, w_m2 + (size_t)l * MLPDIM * CDIM, b_m2 + l * CDIM,
            ph, NTOK, CDIM, MLPDIM, 1);
    }

    ln_kernel<<<NTOK, 256>>>(ph, nullptr, nullptr, pa, 1e-5f, 0);
    outhead_kernel<<<NTOK, 64>>>(pa, w_out, b_out);
    post_kernel<<<(NTOK * NGAUSS + 255) / 256, 256>>>(coords, perturb, out);
}

// round 3
// speedup vs baseline: 2.5216x; 1.3237x over previous
#include <cuda_runtime.h>
#include <cuda_bf16.h>
#include <math.h>
#include <stdint.h>

// ---------------------------------------------------------------------------
// GSDecoder: 8-layer windowed transformer, N=4096, C=512, H=8, DH=64,
// window=512, MLP=2048, out head 56, splat postprocess.
// Round 3: GEMMs bf16x3 tensor cores (round 2) + flash attention on tensor
// cores with the same bf16x3 split scheme.
// ---------------------------------------------------------------------------

#define NTOK   4096
#define CDIM   512
#define HEADS  8
#define DHEAD  64
#define LAYERS 8
#define MLPDIM 2048
#define OUTC   56
#define NGAUSS 4

// ------------------------- scratch (device globals) ------------------------
__device__ float g_h   [NTOK * CDIM];
__device__ float g_a   [NTOK * CDIM];
__device__ float g_qkv [NTOK * 3 * CDIM];
__device__ float g_attn[NTOK * CDIM];
__device__ float g_mlp [NTOK * MLPDIM];
__device__ float g_out [NTOK * OUTC];

// ------------------------------ helpers ------------------------------------
__device__ __forceinline__ float gelu_f(float x) {
    float x3 = x * x * x;
    return 0.5f * x * (1.0f + tanhf(0.7978845608028654f * (x + 0.044715f * x3)));
}

__device__ __forceinline__ void ldsm_x4(unsigned* r, unsigned addr) {
    asm volatile("ldmatrix.sync.aligned.m8n8.x4.shared.b16 {%0,%1,%2,%3}, [%4];"
                 : "=r"(r[0]), "=r"(r[1]), "=r"(r[2]), "=r"(r[3]) : "r"(addr));
}
__device__ __forceinline__ void ldsm_x4t(unsigned* r, unsigned addr) {
    asm volatile("ldmatrix.sync.aligned.m8n8.x4.trans.shared.b16 {%0,%1,%2,%3}, [%4];"
                 : "=r"(r[0]), "=r"(r[1]), "=r"(r[2]), "=r"(r[3]) : "r"(addr));
}
__device__ __forceinline__ void ldsm_x2t(unsigned* r, unsigned addr) {
    asm volatile("ldmatrix.sync.aligned.m8n8.x2.trans.shared.b16 {%0,%1}, [%2];"
                 : "=r"(r[0]), "=r"(r[1]) : "r"(addr));
}
__device__ __forceinline__ void mma16816(float* c, const unsigned* a, const unsigned* b) {
    asm volatile("mma.sync.aligned.m16n8k16.row.col.f32.bf16.bf16.f32 "
                 "{%0,%1,%2,%3}, {%4,%5,%6,%7}, {%8,%9}, {%0,%1,%2,%3};"
                 : "+f"(c[0]), "+f"(c[1]), "+f"(c[2]), "+f"(c[3])
                 : "r"(a[0]), "r"(a[1]), "r"(a[2]), "r"(a[3]),
                   "r"(b[0]), "r"(b[1]));
}

__device__ __forceinline__ void split4(float4 v, __nv_bfloat16* h, __nv_bfloat16* l) {
    float x0 = v.x, x1 = v.y, x2 = v.z, x3 = v.w;
    __nv_bfloat16 h0 = __float2bfloat16_rn(x0);
    __nv_bfloat16 h1 = __float2bfloat16_rn(x1);
    __nv_bfloat16 h2 = __float2bfloat16_rn(x2);
    __nv_bfloat16 h3 = __float2bfloat16_rn(x3);
    __nv_bfloat16 l0 = __float2bfloat16_rn(x0 - __bfloat162float(h0));
    __nv_bfloat16 l1 = __float2bfloat16_rn(x1 - __bfloat162float(h1));
    __nv_bfloat16 l2 = __float2bfloat16_rn(x2 - __bfloat162float(h2));
    __nv_bfloat16 l3 = __float2bfloat16_rn(x3 - __bfloat162float(h3));
    ((__nv_bfloat162*)h)[0] = __halves2bfloat162(h0, h1);
    ((__nv_bfloat162*)h)[1] = __halves2bfloat162(h2, h3);
    ((__nv_bfloat162*)l)[0] = __halves2bfloat162(l0, l1);
    ((__nv_bfloat162*)l)[1] = __halves2bfloat162(l2, l3);
}

__device__ __forceinline__ void pack_hl(float x, float y, unsigned& hi, unsigned& lo) {
    __nv_bfloat16 hx = __float2bfloat16_rn(x);
    __nv_bfloat16 hy = __float2bfloat16_rn(y);
    __nv_bfloat16 lx = __float2bfloat16_rn(x - __bfloat162float(hx));
    __nv_bfloat16 ly = __float2bfloat16_rn(y - __bfloat162float(hy));
    __nv_bfloat162 H = __halves2bfloat162(hx, hy);
    __nv_bfloat162 L = __halves2bfloat162(lx, ly);
    hi = *(unsigned*)&H;
    lo = *(unsigned*)&L;
}

// ------------------------------ embed + PE ---------------------------------
__global__ void embed_kernel(const float* __restrict__ feats,
                             const int*   __restrict__ coords,
                             const float* __restrict__ ex,
                             const float* __restrict__ ey,
                             const float* __restrict__ ez,
                             const float* __restrict__ w_in,
                             const float* __restrict__ b_in)
{
    int n = blockIdx.x;
    int c = threadIdx.x;
    const float* f = feats + (size_t)n * 8;
    float acc = b_in[c];
#pragma unroll
    for (int l = 0; l < 8; l++) acc += f[l] * w_in[l * CDIM + c];

    int cx = coords[n * 4 + 1];
    int cy = coords[n * 4 + 2];
    int cz = coords[n * 4 + 3];
    float pe;
    if (c < 170)      pe = ex[cx * 170 + c];
    else if (c < 340) pe = ey[cy * 170 + (c - 170)];
    else              pe = ez[cz * 172 + (c - 340)];
    g_h[(size_t)n * CDIM + c] = acc + pe;
}

// ------------------------------ layernorm ----------------------------------
__global__ void __launch_bounds__(256)
ln_kernel(const float* __restrict__ x,
          const float* __restrict__ g,
          const float* __restrict__ b,
          float* __restrict__ out,
          float eps, int has_gb)
{
    int n   = blockIdx.x;
    int tid = threadIdx.x;
    const float* xr = x + (size_t)n * CDIM;
    float v0 = xr[tid], v1 = xr[tid + 256];
    float s  = v0 + v1;
    float s2 = v0 * v0 + v1 * v1;
#pragma unroll
    for (int off = 16; off; off >>= 1) {
        s  += __shfl_xor_sync(0xffffffffu, s,  off);
        s2 += __shfl_xor_sync(0xffffffffu, s2, off);
    }
    __shared__ float sh[16];
    __shared__ float stats[2];
    int wid = tid >> 5, lane = tid & 31;
    if (lane == 0) { sh[wid] = s; sh[wid + 8] = s2; }
    __syncthreads();
    if (tid == 0) {
        float ts = 0.f, ts2 = 0.f;
#pragma unroll
        for (int i = 0; i < 8; i++) { ts += sh[i]; ts2 += sh[i + 8]; }
        float mean = ts * (1.0f / 512.0f);
        float var  = ts2 * (1.0f / 512.0f) - mean * mean;
        if (var < 0.f) var = 0.f;
        stats[0] = mean;
        stats[1] = rsqrtf(var + eps);
    }
    __syncthreads();
    float mean = stats[0], r = stats[1];
    float o0 = (v0 - mean) * r;
    float o1 = (v1 - mean) * r;
    if (has_gb) {
        o0 = o0 * g[tid]       + b[tid];
        o1 = o1 * g[tid + 256] + b[tid + 256];
    }
    float* orow = out + (size_t)n * CDIM;
    orow[tid] = o0; orow[tid + 256] = o1;
}

// -------------------- tensor-core GEMM (bf16x3 split) ----------------------
#define BM 128
#define BN 128
#define BK 16
#define APAD 24
#define BPAD 136

__global__ void __launch_bounds__(256)
gemm_tc_kernel(const float* __restrict__ A, const float* __restrict__ B,
               const float* __restrict__ bias, float* __restrict__ C,
               int M, int N, int K, int epi)
{
    __shared__ __align__(16) __nv_bfloat16 sA[2][2][BM * APAD];
    __shared__ __align__(16) __nv_bfloat16 sB[2][2][BK * BPAD];

    const int tid  = threadIdx.x;
    const int wid  = tid >> 5;
    const int lane = tid & 31;
    const int n0 = blockIdx.x * BN;
    const int m0 = blockIdx.y * BM;
    const int wm = (wid >> 2) * 64;
    const int wn = (wid & 3) * 32;

    float acc[4][4][4];
#pragma unroll
    for (int i = 0; i < 4; i++)
#pragma unroll
        for (int j = 0; j < 4; j++)
#pragma unroll
            for (int k = 0; k < 4; k++) acc[i][j][k] = 0.f;

    const int a_row0 = tid >> 2;
    const int a_kc   = (tid & 3) << 2;
    const int b_kr0  = tid >> 5;
    const int b_nc   = (lane) << 2;

    float4 ra[2], rb[2];

#pragma unroll
    for (int i = 0; i < 2; i++) {
        ra[i] = *(const float4*)(A + (size_t)(m0 + a_row0 + 64 * i) * K + a_kc);
        rb[i] = *(const float4*)(B + (size_t)(b_kr0 + 8 * i) * N + n0 + b_nc);
    }
#pragma unroll
    for (int i = 0; i < 2; i++) {
        int offA = (a_row0 + 64 * i) * APAD + a_kc;
        split4(ra[i], &sA[0][0][offA], &sA[0][1][offA]);
        int offB = (b_kr0 + 8 * i) * BPAD + b_nc;
        split4(rb[i], &sB[0][0][offB], &sB[0][1][offB]);
    }
    __syncthreads();

    const int KT = K / BK;
    for (int kt = 0; kt < KT; kt++) {
        int buf = kt & 1;
        if (kt + 1 < KT) {
            int k0 = (kt + 1) * BK;
#pragma unroll
            for (int i = 0; i < 2; i++) {
                ra[i] = *(const float4*)(A + (size_t)(m0 + a_row0 + 64 * i) * K + k0 + a_kc);
                rb[i] = *(const float4*)(B + (size_t)(k0 + b_kr0 + 8 * i) * N + n0 + b_nc);
            }
        }

        unsigned ah[4][4], al[4][4], bh[4][2], bl[4][2];
        {
            unsigned aAddrH = (unsigned)__cvta_generic_to_shared(
                &sA[buf][0][(wm + (lane & 15)) * APAD + ((lane >> 4) << 3)]);
            unsigned aAddrL = (unsigned)__cvta_generic_to_shared(
                &sA[buf][1][(wm + (lane & 15)) * APAD + ((lane >> 4) << 3)]);
#pragma unroll
            for (int mb = 0; mb < 4; mb++) {
                ldsm_x4(ah[mb], aAddrH + mb * (16 * APAD * 2));
                ldsm_x4(al[mb], aAddrL + mb * (16 * APAD * 2));
            }
            unsigned bAddrH = (unsigned)__cvta_generic_to_shared(
                &sB[buf][0][(lane & 15) * BPAD + wn]);
            unsigned bAddrL = (unsigned)__cvta_generic_to_shared(
                &sB[buf][1][(lane & 15) * BPAD + wn]);
#pragma unroll
            for (int nb = 0; nb < 4; nb++) {
                ldsm_x2t(bh[nb], bAddrH + nb * 16);
                ldsm_x2t(bl[nb], bAddrL + nb * 16);
            }
        }
#pragma unroll
        for (int mb = 0; mb < 4; mb++)
#pragma unroll
            for (int nb = 0; nb < 4; nb++)
                mma16816(acc[mb][nb], ah[mb], bh[nb]);
#pragma unroll
        for (int mb = 0; mb < 4; mb++)
#pragma unroll
            for (int nb = 0; nb < 4; nb++)
                mma16816(acc[mb][nb], al[mb], bh[nb]);
#pragma unroll
        for (int mb = 0; mb < 4; mb++)
#pragma unroll
            for (int nb = 0; nb < 4; nb++)
                mma16816(acc[mb][nb], ah[mb], bl[nb]);

        if (kt + 1 < KT) {
            int nbuf = buf ^ 1;
#pragma unroll
            for (int i = 0; i < 2; i++) {
                int offA = (a_row0 + 64 * i) * APAD + a_kc;
                split4(ra[i], &sA[nbuf][0][offA], &sA[nbuf][1][offA]);
                int offB = (b_kr0 + 8 * i) * BPAD + b_nc;
                split4(rb[i], &sB[nbuf][0][offB], &sB[nbuf][1][offB]);
            }
        }
        __syncthreads();
    }

#pragma unroll
    for (int mb = 0; mb < 4; mb++) {
        int m = m0 + wm + mb * 16 + (lane >> 2);
#pragma unroll
        for (int nb = 0; nb < 4; nb++) {
            int n = n0 + wn + nb * 8 + (lane & 3) * 2;
            float2 bv = *(const float2*)(bias + n);
            float c0 = acc[mb][nb][0] + bv.x;
            float c1 = acc[mb][nb][1] + bv.y;
            float c2 = acc[mb][nb][2] + bv.x;
            float c3 = acc[mb][nb][3] + bv.y;
            float* p0 = C + (size_t)m * N + n;
            float* p1 = C + (size_t)(m + 8) * N + n;
            if (epi == 1) {
                float2 r0 = *(float2*)p0;
                float2 r1 = *(float2*)p1;
                c0 += r0.x; c1 += r0.y; c2 += r1.x; c3 += r1.y;
            } else if (epi == 2) {
                c0 = gelu_f(c0); c1 = gelu_f(c1);
                c2 = gelu_f(c2); c3 = gelu_f(c3);
            }
            *(float2*)p0 = make_float2(c0, c1);
            *(float2*)p1 = make_float2(c2, c3);
        }
    }
}

// ------------------- flash attention on tensor cores -----------------------
// grid (8 qtiles, 8 heads, 8 windows), 128 threads (4 warps, m16 each).
// bf16x3 split for both QK^T and PV. smem stride 88 bf16 (176B, 16B-aligned,
// bank-conflict-free for ldmatrix).
#define ASTR 88
#define AQH  0
#define AQL  (64 * ASTR)
#define AKH  (2 * 64 * ASTR)
#define AKL  (3 * 64 * ASTR)
#define AVH  (4 * 64 * ASTR)
#define AVL  (5 * 64 * ASTR)
#define ATT_SMEM (6 * 64 * ASTR * 2)

__global__ void __launch_bounds__(128)
attn_mma_kernel(const float* __restrict__ qkv, float* __restrict__ o)
{
    extern __shared__ __align__(16) __nv_bfloat16 sm[];

    const int tid  = threadIdx.x;
    const int wid  = tid >> 5;
    const int lane = tid & 31;
    const int qt = blockIdx.x, h = blockIdx.y, w = blockIdx.z;
    const int tok0 = w * 512;
    const int q0   = qt * 64;
    const int qoff = h * DHEAD;
    const int koff = CDIM + h * DHEAD;
    const int voff = 2 * CDIM + h * DHEAD;
    const int wm   = wid * 16;

    // ---- stage Q (pre-scaled by 1/8, exact) ----
#pragma unroll
    for (int i = 0; i < 8; i++) {
        int idx = tid + i * 128;
        int r = idx >> 4, c4 = (idx & 15) << 2;
        float4 v = *(const float4*)(qkv + (size_t)(tok0 + q0 + r) * (3 * CDIM) + qoff + c4);
        v.x *= 0.125f; v.y *= 0.125f; v.z *= 0.125f; v.w *= 0.125f;
        split4(v, &sm[AQH + r * ASTR + c4], &sm[AQL + r * ASTR + c4]);
    }
    __syncthreads();

    // ---- Q fragments in registers (persist across key loop) ----
    unsigned qh[4][4], ql[4][4];
    {
        unsigned baseH = (unsigned)__cvta_generic_to_shared(&sm[AQH]);
        unsigned baseL = (unsigned)__cvta_generic_to_shared(&sm[AQL]);
        int row = wm + (lane & 15);
        int coloff = (lane >> 4) << 3;
#pragma unroll
        for (int ks = 0; ks < 4; ks++) {
            unsigned off = (unsigned)(row * ASTR + ks * 16 + coloff) * 2;
            ldsm_x4(qh[ks], baseH + off);
            ldsm_x4(ql[ks], baseL + off);
        }
    }

    float m0 = -1e30f, m1 = -1e30f, l0 = 0.f, l1 = 0.f;
    float oacc[8][4];
#pragma unroll
    for (int i = 0; i < 8; i++)
#pragma unroll
        for (int j = 0; j < 4; j++) oacc[i][j] = 0.f;

    const unsigned bKH = (unsigned)__cvta_generic_to_shared(&sm[AKH]);
    const unsigned bKL = (unsigned)__cvta_generic_to_shared(&sm[AKL]);
    const unsigned bVH = (unsigned)__cvta_generic_to_shared(&sm[AVH]);
    const unsigned bVL = (unsigned)__cvta_generic_to_shared(&sm[AVL]);

    // K B-frag address (non-trans x4: two n8 blocks per load)
    const int k_key  = ((lane >> 4) << 3) + (lane & 7);
    const int k_kc   = ((lane >> 3) & 1) << 3;
    // V B-frag address (trans x4: two n8 blocks per load)
    const int v_kr   = (((lane >> 3) & 1) << 3) + (lane & 7);
    const int v_col  = (lane >> 4) << 3;

    for (int kt = 0; kt < 8; kt++) {
        __syncthreads();
#pragma unroll
        for (int i = 0; i < 8; i++) {
            int idx = tid + i * 128;
            int r = idx >> 4, c4 = (idx & 15) << 2;
            size_t rowb = (size_t)(tok0 + kt * 64 + r) * (3 * CDIM);
            float4 vk = *(const float4*)(qkv + rowb + koff + c4);
            split4(vk, &sm[AKH + r * ASTR + c4], &sm[AKL + r * ASTR + c4]);
            float4 vv = *(const float4*)(qkv + rowb + voff + c4);
            split4(vv, &sm[AVH + r * ASTR + c4], &sm[AVL + r * ASTR + c4]);
        }
        __syncthreads();

        // ---- S = Q K^T (x3) ----
        float s[8][4];
#pragma unroll
        for (int i = 0; i < 8; i++)
#pragma unroll
            for (int j = 0; j < 4; j++) s[i][j] = 0.f;

#pragma unroll
        for (int p = 0; p < 4; p++) {
#pragma unroll
            for (int ks = 0; ks < 4; ks++) {
                unsigned kb_h[4], kb_l[4];
                unsigned off = (unsigned)((p * 16 + k_key) * ASTR + ks * 16 + k_kc) * 2;
                ldsm_x4(kb_h, bKH + off);
                ldsm_x4(kb_l, bKL + off);
                mma16816(s[2 * p],     qh[ks], &kb_h[0]);
                mma16816(s[2 * p],     ql[ks], &kb_h[0]);
                mma16816(s[2 * p],     qh[ks], &kb_l[0]);
                mma16816(s[2 * p + 1], qh[ks], &kb_h[2]);
                mma16816(s[2 * p + 1], ql[ks], &kb_h[2]);
                mma16816(s[2 * p + 1], qh[ks], &kb_l[2]);
            }
        }

        // ---- online softmax (rows: lane>>2 and +8) ----
        float mx0 = -1e30f, mx1 = -1e30f;
#pragma unroll
        for (int nb = 0; nb < 8; nb++) {
            mx0 = fmaxf(mx0, fmaxf(s[nb][0], s[nb][1]));
            mx1 = fmaxf(mx1, fmaxf(s[nb][2], s[nb][3]));
        }
        mx0 = fmaxf(mx0, __shfl_xor_sync(0xffffffffu, mx0, 1));
        mx0 = fmaxf(mx0, __shfl_xor_sync(0xffffffffu, mx0, 2));
        mx1 = fmaxf(mx1, __shfl_xor_sync(0xffffffffu, mx1, 1));
        mx1 = fmaxf(mx1, __shfl_xor_sync(0xffffffffu, mx1, 2));

        float nm0 = fmaxf(m0, mx0);
        float nm1 = fmaxf(m1, mx1);
        float al0 = __expf(m0 - nm0);
        float al1 = __expf(m1 - nm1);
        m0 = nm0; m1 = nm1;

        float sum0 = 0.f, sum1 = 0.f;
#pragma unroll
        for (int nb = 0; nb < 8; nb++) {
            s[nb][0] = __expf(s[nb][0] - nm0);
            s[nb][1] = __expf(s[nb][1] - nm0);
            s[nb][2] = __expf(s[nb][2] - nm1);
            s[nb][3] = __expf(s[nb][3] - nm1);
            sum0 += s[nb][0] + s[nb][1];
            sum1 += s[nb][2] + s[nb][3];
        }
        sum0 += __shfl_xor_sync(0xffffffffu, sum0, 1);
        sum0 += __shfl_xor_sync(0xffffffffu, sum0, 2);
        sum1 += __shfl_xor_sync(0xffffffffu, sum1, 1);
        sum1 += __shfl_xor_sync(0xffffffffu, sum1, 2);
        l0 = l0 * al0 + sum0;
        l1 = l1 * al1 + sum1;

#pragma unroll
        for (int nb = 0; nb < 8; nb++) {
            oacc[nb][0] *= al0; oacc[nb][1] *= al0;
            oacc[nb][2] *= al1; oacc[nb][3] *= al1;
        }

        // ---- O += P V (x3); P frag = S C-frag reused as A-frag ----
#pragma unroll
        for (int kk = 0; kk < 4; kk++) {
            unsigned pa_h[4], pa_l[4];
            pack_hl(s[2 * kk][0],     s[2 * kk][1],     pa_h[0], pa_l[0]);
            pack_hl(s[2 * kk][2],     s[2 * kk][3],     pa_h[1], pa_l[1]);
            pack_hl(s[2 * kk + 1][0], s[2 * kk + 1][1], pa_h[2], pa_l[2]);
            pack_hl(s[2 * kk + 1][2], s[2 * kk + 1][3], pa_h[3], pa_l[3]);
#pragma unroll
            for (int p = 0; p < 4; p++) {
                unsigned vb_h[4], vb_l[4];
                unsigned off = (unsigned)((kk * 16 + v_kr) * ASTR + p * 16 + v_col) * 2;
                ldsm_x4t(vb_h, bVH + off);
                ldsm_x4t(vb_l, bVL + off);
                mma16816(oacc[2 * p],     pa_h, &vb_h[0]);
                mma16816(oacc[2 * p],     pa_l, &vb_h[0]);
                mma16816(oacc[2 * p],     pa_h, &vb_l[0]);
                mma16816(oacc[2 * p + 1], pa_h, &vb_h[2]);
                mma16816(oacc[2 * p + 1], pa_l, &vb_h[2]);
                mma16816(oacc[2 * p + 1], pa_h, &vb_l[2]);
            }
        }
    }

    // ---- epilogue ----
    float i0 = 1.0f / l0, i1 = 1.0f / l1;
    int r0  = tok0 + q0 + wm + (lane >> 2);
    int col = h * DHEAD + ((lane & 3) << 1);
#pragma unroll
    for (int nb = 0; nb < 8; nb++) {
        *(float2*)(o + (size_t)r0 * CDIM + col + nb * 8) =
            make_float2(oacc[nb][0] * i0, oacc[nb][1] * i0);
        *(float2*)(o + (size_t)(r0 + 8) * CDIM + col + nb * 8) =
            make_float2(oacc[nb][2] * i1, oacc[nb][3] * i1);
    }
}

// ----------------------------- out head ------------------------------------
__global__ void outhead_kernel(const float* __restrict__ a,
                               const float* __restrict__ w,
                               const float* __restrict__ b)
{
    __shared__ float row[CDIM];
    int n = blockIdx.x;
    for (int i = threadIdx.x; i < CDIM; i += 64)
        row[i] = a[(size_t)n * CDIM + i];
    __syncthreads();
    int oc = threadIdx.x;
    if (oc < OUTC) {
        float acc = b[oc];
#pragma unroll 8
        for (int k = 0; k < CDIM; k++)
            acc += row[k] * w[k * OUTC + oc];
        g_out[n * OUTC + oc] = acc;
    }
}

// ---------------------------- postprocess ----------------------------------
__global__ void post_kernel(const int* __restrict__ coords,
                            const float* __restrict__ perturb,
                            float* __restrict__ out)
{
    int idx = blockIdx.x * 256 + threadIdx.x;
    if (idx >= NTOK * NGAUSS) return;
    int n = idx >> 2, g = idx & 3;
    const float* r = g_out + n * OUTC;
#pragma unroll
    for (int j = 0; j < 3; j++) {
        float off = tanhf(r[g * 3 + j] + perturb[g * 3 + j]) * 4.8828125e-4f;
        float xb  = ((float)coords[n * 4 + 1 + j] + 0.5f) * 0.0625f;
        out[idx * 3 + j]          = xb + off;
        out[49152 + idx * 3 + j]  = r[12 + g * 3 + j];
        out[98304 + idx * 3 + j]  = r[24 + g * 3 + j];
    }
#pragma unroll
    for (int j = 0; j < 4; j++)
        out[147456 + idx * 4 + j] = r[36 + g * 4 + j];
    out[212992 + idx] = r[52 + g];
}

// ------------------------------- launch ------------------------------------
extern "C" void kernel_launch(void* const* d_in, const int* in_sizes, int n_in,
                              void* d_out, int out_size)
{
    const float* feats   = (const float*)d_in[0];
    const int*   coords  = (const int*)  d_in[1];
    const float* emb_x   = (const float*)d_in[2];
    const float* emb_y   = (const float*)d_in[3];
    const float* emb_z   = (const float*)d_in[4];
    const float* w_in    = (const float*)d_in[5];
    const float* b_in    = (const float*)d_in[6];
    const float* ln1_g   = (const float*)d_in[7];
    const float* ln1_b   = (const float*)d_in[8];
    const float* w_qkv   = (const float*)d_in[9];
    const float* b_qkv   = (const float*)d_in[10];
    const float* w_o     = (const float*)d_in[11];
    const float* b_o     = (const float*)d_in[12];
    const float* ln2_g   = (const float*)d_in[13];
    const float* ln2_b   = (const float*)d_in[14];
    const float* w_m1    = (const float*)d_in[15];
    const float* b_m1    = (const float*)d_in[16];
    const float* w_m2    = (const float*)d_in[17];
    const float* b_m2    = (const float*)d_in[18];
    const float* w_out   = (const float*)d_in[19];
    const float* b_out   = (const float*)d_in[20];
    const float* perturb = (const float*)d_in[21];
    float* out = (float*)d_out;

    float *ph, *pa, *pqkv, *pattn, *pmlp;
    cudaGetSymbolAddress((void**)&ph,    g_h);
    cudaGetSymbolAddress((void**)&pa,    g_a);
    cudaGetSymbolAddress((void**)&pqkv,  g_qkv);
    cudaGetSymbolAddress((void**)&pattn, g_attn);
    cudaGetSymbolAddress((void**)&pmlp,  g_mlp);

    cudaFuncSetAttribute(attn_mma_kernel,
                         cudaFuncAttributeMaxDynamicSharedMemorySize, ATT_SMEM);

    embed_kernel<<<NTOK, CDIM>>>(feats, coords, emb_x, emb_y, emb_z, w_in, b_in);

    for (int l = 0; l < LAYERS; l++) {
        ln_kernel<<<NTOK, 256>>>(ph, ln1_g + l * CDIM, ln1_b + l * CDIM,
                                 pa, 1e-6f, 1);
        gemm_tc_kernel<<<dim3(3 * CDIM / BN, NTOK / BM), 256>>>(
            pa, w_qkv + (size_t)l * CDIM * 3 * CDIM, b_qkv + l * 3 * CDIM,
            pqkv, NTOK, 3 * CDIM, CDIM, 0);
        attn_mma_kernel<<<dim3(8, HEADS, 8), 128, ATT_SMEM>>>(pqkv, pattn);
        gemm_tc_kernel<<<dim3(CDIM / BN, NTOK / BM), 256>>>(
            pattn, w_o + (size_t)l * CDIM * CDIM, b_o + l * CDIM,
            ph, NTOK, CDIM, CDIM, 1);
        ln_kernel<<<NTOK, 256>>>(ph, ln2_g + l * CDIM, ln2_b + l * CDIM,
                                 pa, 1e-6f, 1);
        gemm_tc_kernel<<<dim3(MLPDIM / BN, NTOK / BM), 256>>>(
            pa, w_m1 + (size_t)l * CDIM * MLPDIM, b_m1 + l * MLPDIM,
            pmlp, NTOK, MLPDIM, CDIM, 2);
        gemm_tc_kernel<<<dim3(CDIM / BN, NTOK / BM), 256>>>(
            pmlp, w_m2 + (size_t)l * MLPDIM * CDIM, b_m2 + l * CDIM,
            ph, NTOK, CDIM, MLPDIM, 1);
    }

    ln_kernel<<<NTOK, 256>>>(ph, nullptr, nullptr, pa, 1e-5f, 0);
    outhead_kernel<<<NTOK, 64>>>(pa, w_out, b_out);
    post_kernel<<<(NTOK * NGAUSS + 255) / 256, 256>>>(coords, perturb, out);
}